// round 5
// baseline (speedup 1.0000x reference)
#include <cuda_runtime.h>
#include <cuda_bf16.h>
#include <cstdint>

// ---------------------------------------------------------------------------
// out[b,v] = h2[b] . emb[v] + c[b]   (rank-16 reduction of the final GEMM)
//   h2[b] = hidden[b] @ fc0_w (16),  c[b] = hidden[b] . fc0_b
// k2: k-packed f32x2, c folded into acc init as (c,0); epilogue = 1 FADD per
//     output (lo+hi), no repacking MOVs.
// ---------------------------------------------------------------------------

#define VOCAB 128000
#define EMB   32
#define HALF  16
#define BATCH 1024
#define SEQ   50

__device__ __align__(16) float g_h2[BATCH * HALF];
__device__ __align__(16) float g_c[BATCH];

typedef unsigned long long ull;

__device__ __forceinline__ ull pk2(float lo, float hi) {
    ull r; asm("mov.b64 %0, {%1, %2};" : "=l"(r) : "f"(lo), "f"(hi)); return r;
}
__device__ __forceinline__ void unpk2(ull v, float& lo, float& hi) {
    asm("mov.b64 {%0, %1}, %2;" : "=f"(lo), "=f"(hi) : "l"(v));
}
__device__ __forceinline__ ull mul2(ull a, ull b) {
    ull d; asm("mul.rn.f32x2 %0, %1, %2;" : "=l"(d) : "l"(a), "l"(b)); return d;
}
__device__ __forceinline__ ull fma2(ull a, ull b, ull c) {
    ull d; asm("fma.rn.f32x2 %0, %1, %2, %3;" : "=l"(d) : "l"(a), "l"(b), "l"(c)); return d;
}
__device__ __forceinline__ ull add2(ull a, ull b) {
    ull d; asm("add.rn.f32x2 %0, %1, %2;" : "=l"(d) : "l"(a), "l"(b)); return d;
}
__device__ __forceinline__ float tanh_fast(float x) {
    float y; asm("tanh.approx.f32 %0, %1;" : "=f"(y) : "f"(x)); return y;
}

// ---------------------------------------------------------------------------
// Kernel 1: 4 batch rows/block, 2 warps/row, lane = seq position.
// ---------------------------------------------------------------------------
#define K1_ROWS 4
#define EPAD 36

__global__ void __launch_bounds__(256) k1_attend(
    const int*   __restrict__ text,
    const float* __restrict__ emb,
    const float* __restrict__ fc0_w,
    const float* __restrict__ fc0_b,
    const float* __restrict__ wq,
    const float* __restrict__ wk,
    const float* __restrict__ av,
    const float* __restrict__ out_w,
    const float* __restrict__ out_b)
{
    __shared__ float s_fc0w[EMB * HALF];
    __shared__ float s_W[EMB * EMB];
    __shared__ float s_outw[EMB * 65];
    __shared__ float s_av[EMB], s_fc0b[EMB], s_outb[EMB];
    __shared__ int   s_tok[K1_ROWS][SEQ];
    __shared__ float s_emb[K1_ROWS][SEQ * EPAD];
    __shared__ float s_sc[K1_ROWS][SEQ];
    __shared__ float s_vec[K1_ROWS][2][EMB];

    const int tid = threadIdx.x;
    const int b0  = blockIdx.x * K1_ROWS;

    for (int i = tid; i < EMB * HALF; i += 256) s_fc0w[i] = fc0_w[i];
    for (int i = tid; i < EMB * EMB; i += 256)  s_W[i] = wq[i] + wk[i];
    for (int i = tid; i < EMB * 2 * EMB; i += 256) {
        int r = i >> 6, c = i & 63;
        s_outw[r * 65 + c] = out_w[i];
    }
    if (tid < EMB) { s_av[tid] = av[tid]; s_fc0b[tid] = fc0_b[tid]; s_outb[tid] = out_b[tid]; }
    for (int i = tid; i < K1_ROWS * SEQ; i += 256)
        s_tok[i / SEQ][i % SEQ] = text[b0 * SEQ + i];
    __syncthreads();

    const int w    = tid >> 5;
    const int lane = tid & 31;
    const int row  = w >> 1;
    const int sidx = ((w & 1) << 5) + lane;
    const bool act = sidx < SEQ;

    const int tok = act ? s_tok[row][sidx] : 0;
    const bool valid = act && (tok != 0) && (tok != 1);
    const float4* er = reinterpret_cast<const float4*>(emb + (size_t)tok * HALF);
    float4 q0 = __ldg(er + 0), q1 = __ldg(er + 1), q2 = __ldg(er + 2), q3 = __ldg(er + 3);
    ull me[8];
    me[0] = pk2(q0.x, q0.y); me[1] = pk2(q0.z, q0.w);
    me[2] = pk2(q1.x, q1.y); me[3] = pk2(q1.z, q1.w);
    me[4] = pk2(q2.x, q2.y); me[5] = pk2(q2.z, q2.w);
    me[6] = pk2(q3.x, q3.y); me[7] = pk2(q3.z, q3.w);

    float embS[EMB];
    const float msk = valid ? 1.0f : 0.0f;
#pragma unroll
    for (int e = 0; e < EMB; e++) {
        const ulonglong2* wr = reinterpret_cast<const ulonglong2*>(s_fc0w + e * HALF);
        ulonglong2 wa = wr[0], wb = wr[1], wc = wr[2], wd = wr[3];
        ull a0 = mul2(me[0], wa.x); a0 = fma2(me[1], wa.y, a0);
        ull a1 = mul2(me[2], wb.x); a1 = fma2(me[3], wb.y, a1);
        a0 = fma2(me[4], wc.x, a0); a1 = fma2(me[5], wc.y, a1);
        a0 = fma2(me[6], wd.x, a0); a1 = fma2(me[7], wd.y, a1);
        a0 = add2(a0, a1);
        float lo, hi; unpk2(a0, lo, hi);
        embS[e] = (lo + hi + s_fc0b[e]) * msk;
    }

    if (act) {
        float4* dst = reinterpret_cast<float4*>(&s_emb[row][sidx * EPAD]);
#pragma unroll
        for (int qd = 0; qd < 8; qd++)
            dst[qd] = make_float4(embS[qd * 4], embS[qd * 4 + 1], embS[qd * 4 + 2], embS[qd * 4 + 3]);
    }

    ull e2[HALF];
#pragma unroll
    for (int p = 0; p < HALF; p++) e2[p] = pk2(embS[2 * p], embS[2 * p + 1]);

    float score = 0.0f;
#pragma unroll 4
    for (int e = 0; e < EMB; e++) {
        const ulonglong2* wr = reinterpret_cast<const ulonglong2*>(s_W + e * EMB);
        ull a0 = mul2(e2[0], wr[0].x); ull a1 = mul2(e2[1], wr[0].y);
        a0 = fma2(e2[2], wr[1].x, a0); a1 = fma2(e2[3], wr[1].y, a1);
        a0 = fma2(e2[4], wr[2].x, a0); a1 = fma2(e2[5], wr[2].y, a1);
        a0 = fma2(e2[6], wr[3].x, a0); a1 = fma2(e2[7], wr[3].y, a1);
        a0 = fma2(e2[8], wr[4].x, a0); a1 = fma2(e2[9], wr[4].y, a1);
        a0 = fma2(e2[10], wr[5].x, a0); a1 = fma2(e2[11], wr[5].y, a1);
        a0 = fma2(e2[12], wr[6].x, a0); a1 = fma2(e2[13], wr[6].y, a1);
        a0 = fma2(e2[14], wr[7].x, a0); a1 = fma2(e2[15], wr[7].y, a1);
        a0 = add2(a0, a1);
        float lo, hi; unpk2(a0, lo, hi);
        score += tanh_fast(lo + hi) * s_av[e];
    }
    if (act) s_sc[row][sidx] = valid ? score : -1000000000.0f;
    __syncthreads();

    if ((w & 1) == 0) {
        const int e = lane;
        float sc0 = s_sc[row][e];
        float sc1 = (e < SEQ - 32) ? s_sc[row][e + 32] : -3.4e38f;
        float m = fmaxf(sc0, sc1);
#pragma unroll
        for (int o = 16; o > 0; o >>= 1) m = fmaxf(m, __shfl_xor_sync(0xffffffffu, m, o));
        float ex0 = __expf(sc0 - m);
        float ex1 = (e < SEQ - 32) ? __expf(sc1 - m) : 0.0f;
        float ssum = ex0 + ex1;
#pragma unroll
        for (int o = 16; o > 0; o >>= 1) ssum += __shfl_xor_sync(0xffffffffu, ssum, o);
        const float inv = 1.0f / ssum;
        s_sc[row][e] = ex0 * inv;
        if (e < SEQ - 32) s_sc[row][e + 32] = ex1 * inv;
        __syncwarp();

        float sg = 0.0f;
#pragma unroll 2
        for (int s = 0; s < SEQ; s++)
            sg += s_sc[row][s] * s_emb[row][s * EPAD + e];
        s_vec[row][0][e] = sg;
        s_vec[row][1][e] = s_emb[row][(SEQ - 1) * EPAD + e];
        __syncwarp();

        float hid = s_outb[e];
        const float* owr = s_outw + e * 65;
#pragma unroll
        for (int j = 0; j < EMB; j++)
            hid += s_vec[row][0][j] * owr[j] + s_vec[row][1][j] * owr[EMB + j];

        s_vec[row][0][e] = hid;
        __syncwarp();
        if (e < HALF) {
            float a = 0.0f;
#pragma unroll
            for (int j = 0; j < EMB; j++) a += s_vec[row][0][j] * s_fc0w[j * HALF + e];
            g_h2[(b0 + row) * HALF + e] = a;
        }
        float cp = hid * s_fc0b[e];
#pragma unroll
        for (int o = 16; o > 0; o >>= 1) cp += __shfl_xor_sync(0xffffffffu, cp, o);
        if (e == 0) g_c[b0 + row] = cp;
    }
}

// ---------------------------------------------------------------------------
// Kernel 2: out[b,v] = h2[b] . emb[v] + c[b]
// TV=4, k-packed f32x2. Per bb: 4 LDS.128 + 1 LDS.64 + 32 FFMA2 + 4 FADD
// (independent, c pre-folded into every acc init) + 1 STG.128.
// ---------------------------------------------------------------------------
#define K2_THREADS 256
#define K2_BT      128
#define K2_TV      4

__global__ void __launch_bounds__(K2_THREADS, 3) k2_score(
    const float* __restrict__ emb,
    float*       __restrict__ out)
{
    __shared__ float s_h2[K2_BT * HALF];   // plain h2 tile, 8KB
    __shared__ float2 s_c2[K2_BT];         // (c, 0) pairs, 1KB

    const int tid = threadIdx.x;
    const int b0  = blockIdx.y * K2_BT;

    for (int i = tid; i < K2_BT * HALF / 4; i += K2_THREADS)
        reinterpret_cast<float4*>(s_h2)[i] =
            reinterpret_cast<const float4*>(g_h2 + b0 * HALF)[i];
    if (tid < K2_BT) s_c2[tid] = make_float2(g_c[b0 + tid], 0.0f);
    __syncthreads();

    const size_t v0 = ((size_t)blockIdx.x * K2_THREADS + tid) * K2_TV;

    // emb rows v0..v0+3, k-packed pairs straight from memory (no repacking)
    ull ev[K2_TV][8];
#pragma unroll
    for (int v = 0; v < K2_TV; v++) {
        const ulonglong2* ep = reinterpret_cast<const ulonglong2*>(emb + (v0 + v) * HALF);
        ulonglong2 u0 = __ldg(ep + 0), u1 = __ldg(ep + 1),
                   u2 = __ldg(ep + 2), u3 = __ldg(ep + 3);
        ev[v][0] = u0.x; ev[v][1] = u0.y; ev[v][2] = u1.x; ev[v][3] = u1.y;
        ev[v][4] = u2.x; ev[v][5] = u2.y; ev[v][6] = u3.x; ev[v][7] = u3.y;
    }

    const ull* c2p = reinterpret_cast<const ull*>(s_c2);
    float4* optr = reinterpret_cast<float4*>(out + (size_t)b0 * VOCAB + v0);
    const size_t row4 = (size_t)VOCAB / 4;

#pragma unroll 2
    for (int bb = 0; bb < K2_BT; bb++) {
        const ulonglong2* hq = reinterpret_cast<const ulonglong2*>(s_h2 + bb * HALF);
        ulonglong2 hA = hq[0], hB = hq[1], hC = hq[2], hD = hq[3];  // 8 k-pairs
        const ull c20 = c2p[bb];   // (c, 0)

        ull a0 = fma2(ev[0][0], hA.x, c20);
        ull a1 = fma2(ev[1][0], hA.x, c20);
        ull a2 = fma2(ev[2][0], hA.x, c20);
        ull a3 = fma2(ev[3][0], hA.x, c20);
        a0 = fma2(ev[0][1], hA.y, a0); a1 = fma2(ev[1][1], hA.y, a1);
        a2 = fma2(ev[2][1], hA.y, a2); a3 = fma2(ev[3][1], hA.y, a3);
        a0 = fma2(ev[0][2], hB.x, a0); a1 = fma2(ev[1][2], hB.x, a1);
        a2 = fma2(ev[2][2], hB.x, a2); a3 = fma2(ev[3][2], hB.x, a3);
        a0 = fma2(ev[0][3], hB.y, a0); a1 = fma2(ev[1][3], hB.y, a1);
        a2 = fma2(ev[2][3], hB.y, a2); a3 = fma2(ev[3][3], hB.y, a3);
        a0 = fma2(ev[0][4], hC.x, a0); a1 = fma2(ev[1][4], hC.x, a1);
        a2 = fma2(ev[2][4], hC.x, a2); a3 = fma2(ev[3][4], hC.x, a3);
        a0 = fma2(ev[0][5], hC.y, a0); a1 = fma2(ev[1][5], hC.y, a1);
        a2 = fma2(ev[2][5], hC.y, a2); a3 = fma2(ev[3][5], hC.y, a3);
        a0 = fma2(ev[0][6], hD.x, a0); a1 = fma2(ev[1][6], hD.x, a1);
        a2 = fma2(ev[2][6], hD.x, a2); a3 = fma2(ev[3][6], hD.x, a3);
        a0 = fma2(ev[0][7], hD.y, a0); a1 = fma2(ev[1][7], hD.y, a1);
        a2 = fma2(ev[2][7], hD.y, a2); a3 = fma2(ev[3][7], hD.y, a3);

        // out_v = acc.lo + acc.hi  (unpack is register aliasing; 4 indep FADD)
        float l0, h0, l1, h1, l2, h2v, l3, h3;
        unpk2(a0, l0, h0); unpk2(a1, l1, h1);
        unpk2(a2, l2, h2v); unpk2(a3, l3, h3);
        float o0 = l0 + h0;
        float o1 = l1 + h1;
        float o2 = l2 + h2v;
        float o3 = l3 + h3;
        __stcs(optr, make_float4(o0, o1, o2, o3));
        optr += row4;
    }
}

// ---------------------------------------------------------------------------
extern "C" void kernel_launch(void* const* d_in, const int* in_sizes, int n_in,
                              void* d_out, int out_size)
{
    const int*   text   = (const int*)  d_in[0];
    const float* emb    = (const float*)d_in[1];
    const float* fc0_w  = (const float*)d_in[2];
    const float* fc0_b  = (const float*)d_in[3];
    const float* att_wq = (const float*)d_in[4];
    const float* att_wk = (const float*)d_in[5];
    const float* att_v  = (const float*)d_in[6];
    const float* out_w  = (const float*)d_in[7];
    const float* out_b  = (const float*)d_in[8];
    float* out = (float*)d_out;

    k1_attend<<<BATCH / K1_ROWS, 256>>>(text, emb, fc0_w, fc0_b,
                                        att_wq, att_wk, att_v, out_w, out_b);

    dim3 grid(VOCAB / (K2_THREADS * K2_TV), BATCH / K2_BT);  // (125, 8)
    k2_score<<<grid, K2_THREADS>>>(emb, out);
}

// round 6
// speedup vs baseline: 1.8226x; 1.8226x over previous
#include <cuda_runtime.h>
#include <cuda_bf16.h>
#include <cstdint>

// ---------------------------------------------------------------------------
// out[b,v] = h2[b] . emb[v] + c[b]   (rank-16 reduction of the final GEMM)
//   h2[b] = hidden[b] @ fc0_w (16),  c[b] = hidden[b] . fc0_b
// k2: k-packed f32x2, c folded into acc init as (c,0), epilogue lo+hi.
//     unroll 1 + uncapped regs: no spills, stay on the DRAM-write wall.
// ---------------------------------------------------------------------------

#define VOCAB 128000
#define EMB   32
#define HALF  16
#define BATCH 1024
#define SEQ   50

__device__ __align__(16) float g_h2[BATCH * HALF];
__device__ __align__(16) float g_c[BATCH];

typedef unsigned long long ull;

__device__ __forceinline__ ull pk2(float lo, float hi) {
    ull r; asm("mov.b64 %0, {%1, %2};" : "=l"(r) : "f"(lo), "f"(hi)); return r;
}
__device__ __forceinline__ void unpk2(ull v, float& lo, float& hi) {
    asm("mov.b64 {%0, %1}, %2;" : "=f"(lo), "=f"(hi) : "l"(v));
}
__device__ __forceinline__ ull mul2(ull a, ull b) {
    ull d; asm("mul.rn.f32x2 %0, %1, %2;" : "=l"(d) : "l"(a), "l"(b)); return d;
}
__device__ __forceinline__ ull fma2(ull a, ull b, ull c) {
    ull d; asm("fma.rn.f32x2 %0, %1, %2, %3;" : "=l"(d) : "l"(a), "l"(b), "l"(c)); return d;
}
__device__ __forceinline__ ull add2(ull a, ull b) {
    ull d; asm("add.rn.f32x2 %0, %1, %2;" : "=l"(d) : "l"(a), "l"(b)); return d;
}
__device__ __forceinline__ float tanh_fast(float x) {
    float y; asm("tanh.approx.f32 %0, %1;" : "=f"(y) : "f"(x)); return y;
}

// ---------------------------------------------------------------------------
// Kernel 1: 4 batch rows/block, 2 warps/row, lane = seq position.
// ---------------------------------------------------------------------------
#define K1_ROWS 4
#define EPAD 36

__global__ void __launch_bounds__(256) k1_attend(
    const int*   __restrict__ text,
    const float* __restrict__ emb,
    const float* __restrict__ fc0_w,
    const float* __restrict__ fc0_b,
    const float* __restrict__ wq,
    const float* __restrict__ wk,
    const float* __restrict__ av,
    const float* __restrict__ out_w,
    const float* __restrict__ out_b)
{
    __shared__ float s_fc0w[EMB * HALF];
    __shared__ float s_W[EMB * EMB];
    __shared__ float s_outw[EMB * 65];
    __shared__ float s_av[EMB], s_fc0b[EMB], s_outb[EMB];
    __shared__ int   s_tok[K1_ROWS][SEQ];
    __shared__ float s_emb[K1_ROWS][SEQ * EPAD];
    __shared__ float s_sc[K1_ROWS][SEQ];
    __shared__ float s_vec[K1_ROWS][2][EMB];

    const int tid = threadIdx.x;
    const int b0  = blockIdx.x * K1_ROWS;

    for (int i = tid; i < EMB * HALF; i += 256) s_fc0w[i] = fc0_w[i];
    for (int i = tid; i < EMB * EMB; i += 256)  s_W[i] = wq[i] + wk[i];
    for (int i = tid; i < EMB * 2 * EMB; i += 256) {
        int r = i >> 6, c = i & 63;
        s_outw[r * 65 + c] = out_w[i];
    }
    if (tid < EMB) { s_av[tid] = av[tid]; s_fc0b[tid] = fc0_b[tid]; s_outb[tid] = out_b[tid]; }
    for (int i = tid; i < K1_ROWS * SEQ; i += 256)
        s_tok[i / SEQ][i % SEQ] = text[b0 * SEQ + i];
    __syncthreads();

    const int w    = tid >> 5;
    const int lane = tid & 31;
    const int row  = w >> 1;
    const int sidx = ((w & 1) << 5) + lane;
    const bool act = sidx < SEQ;

    const int tok = act ? s_tok[row][sidx] : 0;
    const bool valid = act && (tok != 0) && (tok != 1);
    const float4* er = reinterpret_cast<const float4*>(emb + (size_t)tok * HALF);
    float4 q0 = __ldg(er + 0), q1 = __ldg(er + 1), q2 = __ldg(er + 2), q3 = __ldg(er + 3);
    ull me[8];
    me[0] = pk2(q0.x, q0.y); me[1] = pk2(q0.z, q0.w);
    me[2] = pk2(q1.x, q1.y); me[3] = pk2(q1.z, q1.w);
    me[4] = pk2(q2.x, q2.y); me[5] = pk2(q2.z, q2.w);
    me[6] = pk2(q3.x, q3.y); me[7] = pk2(q3.z, q3.w);

    float embS[EMB];
    const float msk = valid ? 1.0f : 0.0f;
#pragma unroll
    for (int e = 0; e < EMB; e++) {
        const ulonglong2* wr = reinterpret_cast<const ulonglong2*>(s_fc0w + e * HALF);
        ulonglong2 wa = wr[0], wb = wr[1], wc = wr[2], wd = wr[3];
        ull a0 = mul2(me[0], wa.x); a0 = fma2(me[1], wa.y, a0);
        ull a1 = mul2(me[2], wb.x); a1 = fma2(me[3], wb.y, a1);
        a0 = fma2(me[4], wc.x, a0); a1 = fma2(me[5], wc.y, a1);
        a0 = fma2(me[6], wd.x, a0); a1 = fma2(me[7], wd.y, a1);
        a0 = add2(a0, a1);
        float lo, hi; unpk2(a0, lo, hi);
        embS[e] = (lo + hi + s_fc0b[e]) * msk;
    }

    if (act) {
        float4* dst = reinterpret_cast<float4*>(&s_emb[row][sidx * EPAD]);
#pragma unroll
        for (int qd = 0; qd < 8; qd++)
            dst[qd] = make_float4(embS[qd * 4], embS[qd * 4 + 1], embS[qd * 4 + 2], embS[qd * 4 + 3]);
    }

    ull e2[HALF];
#pragma unroll
    for (int p = 0; p < HALF; p++) e2[p] = pk2(embS[2 * p], embS[2 * p + 1]);

    float score = 0.0f;
#pragma unroll 4
    for (int e = 0; e < EMB; e++) {
        const ulonglong2* wr = reinterpret_cast<const ulonglong2*>(s_W + e * EMB);
        ull a0 = mul2(e2[0], wr[0].x); ull a1 = mul2(e2[1], wr[0].y);
        a0 = fma2(e2[2], wr[1].x, a0); a1 = fma2(e2[3], wr[1].y, a1);
        a0 = fma2(e2[4], wr[2].x, a0); a1 = fma2(e2[5], wr[2].y, a1);
        a0 = fma2(e2[6], wr[3].x, a0); a1 = fma2(e2[7], wr[3].y, a1);
        a0 = fma2(e2[8], wr[4].x, a0); a1 = fma2(e2[9], wr[4].y, a1);
        a0 = fma2(e2[10], wr[5].x, a0); a1 = fma2(e2[11], wr[5].y, a1);
        a0 = fma2(e2[12], wr[6].x, a0); a1 = fma2(e2[13], wr[6].y, a1);
        a0 = fma2(e2[14], wr[7].x, a0); a1 = fma2(e2[15], wr[7].y, a1);
        a0 = add2(a0, a1);
        float lo, hi; unpk2(a0, lo, hi);
        score += tanh_fast(lo + hi) * s_av[e];
    }
    if (act) s_sc[row][sidx] = valid ? score : -1000000000.0f;
    __syncthreads();

    if ((w & 1) == 0) {
        const int e = lane;
        float sc0 = s_sc[row][e];
        float sc1 = (e < SEQ - 32) ? s_sc[row][e + 32] : -3.4e38f;
        float m = fmaxf(sc0, sc1);
#pragma unroll
        for (int o = 16; o > 0; o >>= 1) m = fmaxf(m, __shfl_xor_sync(0xffffffffu, m, o));
        float ex0 = __expf(sc0 - m);
        float ex1 = (e < SEQ - 32) ? __expf(sc1 - m) : 0.0f;
        float ssum = ex0 + ex1;
#pragma unroll
        for (int o = 16; o > 0; o >>= 1) ssum += __shfl_xor_sync(0xffffffffu, ssum, o);
        const float inv = 1.0f / ssum;
        s_sc[row][e] = ex0 * inv;
        if (e < SEQ - 32) s_sc[row][e + 32] = ex1 * inv;
        __syncwarp();

        float sg = 0.0f;
#pragma unroll 2
        for (int s = 0; s < SEQ; s++)
            sg += s_sc[row][s] * s_emb[row][s * EPAD + e];
        s_vec[row][0][e] = sg;
        s_vec[row][1][e] = s_emb[row][(SEQ - 1) * EPAD + e];
        __syncwarp();

        float hid = s_outb[e];
        const float* owr = s_outw + e * 65;
#pragma unroll
        for (int j = 0; j < EMB; j++)
            hid += s_vec[row][0][j] * owr[j] + s_vec[row][1][j] * owr[EMB + j];

        s_vec[row][0][e] = hid;
        __syncwarp();
        if (e < HALF) {
            float a = 0.0f;
#pragma unroll
            for (int j = 0; j < EMB; j++) a += s_vec[row][0][j] * s_fc0w[j * HALF + e];
            g_h2[(b0 + row) * HALF + e] = a;
        }
        float cp = hid * s_fc0b[e];
#pragma unroll
        for (int o = 16; o > 0; o >>= 1) cp += __shfl_xor_sync(0xffffffffu, cp, o);
        if (e == 0) g_c[b0 + row] = cp;
    }
}

// ---------------------------------------------------------------------------
// Kernel 2: out[b,v] = h2[b] . emb[v] + c[b]
// TV=4, k-packed f32x2. Per bb: 4 LDS.128 + 1 LDS.64 + 32 FFMA2 + 4 FADD
// + 1 STG.128. unroll 1, regs uncapped (no spills).
// ---------------------------------------------------------------------------
#define K2_THREADS 256
#define K2_BT      128
#define K2_TV      4

__global__ void __launch_bounds__(K2_THREADS) k2_score(
    const float* __restrict__ emb,
    float*       __restrict__ out)
{
    __shared__ float s_h2[K2_BT * HALF];   // plain h2 tile, 8KB
    __shared__ float2 s_c2[K2_BT];         // (c, 0) pairs, 1KB

    const int tid = threadIdx.x;
    const int b0  = blockIdx.y * K2_BT;

    for (int i = tid; i < K2_BT * HALF / 4; i += K2_THREADS)
        reinterpret_cast<float4*>(s_h2)[i] =
            reinterpret_cast<const float4*>(g_h2 + b0 * HALF)[i];
    if (tid < K2_BT) s_c2[tid] = make_float2(g_c[b0 + tid], 0.0f);
    __syncthreads();

    const size_t v0 = ((size_t)blockIdx.x * K2_THREADS + tid) * K2_TV;

    // emb rows v0..v0+3, k-packed pairs straight from memory (no repacking)
    ull ev[K2_TV][8];
#pragma unroll
    for (int v = 0; v < K2_TV; v++) {
        const ulonglong2* ep = reinterpret_cast<const ulonglong2*>(emb + (v0 + v) * HALF);
        ulonglong2 u0 = __ldg(ep + 0), u1 = __ldg(ep + 1),
                   u2 = __ldg(ep + 2), u3 = __ldg(ep + 3);
        ev[v][0] = u0.x; ev[v][1] = u0.y; ev[v][2] = u1.x; ev[v][3] = u1.y;
        ev[v][4] = u2.x; ev[v][5] = u2.y; ev[v][6] = u3.x; ev[v][7] = u3.y;
    }

    const ull* c2p = reinterpret_cast<const ull*>(s_c2);
    float4* optr = reinterpret_cast<float4*>(out + (size_t)b0 * VOCAB + v0);
    const size_t row4 = (size_t)VOCAB / 4;

#pragma unroll 1
    for (int bb = 0; bb < K2_BT; bb++) {
        const ulonglong2* hq = reinterpret_cast<const ulonglong2*>(s_h2 + bb * HALF);
        ulonglong2 hA = hq[0], hB = hq[1], hC = hq[2], hD = hq[3];  // 8 k-pairs
        const ull c20 = c2p[bb];   // (c, 0)

        ull a0 = fma2(ev[0][0], hA.x, c20);
        ull a1 = fma2(ev[1][0], hA.x, c20);
        ull a2 = fma2(ev[2][0], hA.x, c20);
        ull a3 = fma2(ev[3][0], hA.x, c20);
        a0 = fma2(ev[0][1], hA.y, a0); a1 = fma2(ev[1][1], hA.y, a1);
        a2 = fma2(ev[2][1], hA.y, a2); a3 = fma2(ev[3][1], hA.y, a3);
        a0 = fma2(ev[0][2], hB.x, a0); a1 = fma2(ev[1][2], hB.x, a1);
        a2 = fma2(ev[2][2], hB.x, a2); a3 = fma2(ev[3][2], hB.x, a3);
        a0 = fma2(ev[0][3], hB.y, a0); a1 = fma2(ev[1][3], hB.y, a1);
        a2 = fma2(ev[2][3], hB.y, a2); a3 = fma2(ev[3][3], hB.y, a3);
        a0 = fma2(ev[0][4], hC.x, a0); a1 = fma2(ev[1][4], hC.x, a1);
        a2 = fma2(ev[2][4], hC.x, a2); a3 = fma2(ev[3][4], hC.x, a3);
        a0 = fma2(ev[0][5], hC.y, a0); a1 = fma2(ev[1][5], hC.y, a1);
        a2 = fma2(ev[2][5], hC.y, a2); a3 = fma2(ev[3][5], hC.y, a3);
        a0 = fma2(ev[0][6], hD.x, a0); a1 = fma2(ev[1][6], hD.x, a1);
        a2 = fma2(ev[2][6], hD.x, a2); a3 = fma2(ev[3][6], hD.x, a3);
        a0 = fma2(ev[0][7], hD.y, a0); a1 = fma2(ev[1][7], hD.y, a1);
        a2 = fma2(ev[2][7], hD.y, a2); a3 = fma2(ev[3][7], hD.y, a3);

        // out_v = acc.lo + acc.hi  (unpack = register aliasing; 4 indep FADD)
        float l0, h0, l1, h1, l2, h2v, l3, h3;
        unpk2(a0, l0, h0); unpk2(a1, l1, h1);
        unpk2(a2, l2, h2v); unpk2(a3, l3, h3);
        float o0 = l0 + h0;
        float o1 = l1 + h1;
        float o2 = l2 + h2v;
        float o3 = l3 + h3;
        __stcs(optr, make_float4(o0, o1, o2, o3));
        optr += row4;
    }
}

// ---------------------------------------------------------------------------
extern "C" void kernel_launch(void* const* d_in, const int* in_sizes, int n_in,
                              void* d_out, int out_size)
{
    const int*   text   = (const int*)  d_in[0];
    const float* emb    = (const float*)d_in[1];
    const float* fc0_w  = (const float*)d_in[2];
    const float* fc0_b  = (const float*)d_in[3];
    const float* att_wq = (const float*)d_in[4];
    const float* att_wk = (const float*)d_in[5];
    const float* att_v  = (const float*)d_in[6];
    const float* out_w  = (const float*)d_in[7];
    const float* out_b  = (const float*)d_in[8];
    float* out = (float*)d_out;

    k1_attend<<<BATCH / K1_ROWS, 256>>>(text, emb, fc0_w, fc0_b,
                                        att_wq, att_wk, att_v, out_w, out_b);

    dim3 grid(VOCAB / (K2_THREADS * K2_TV), BATCH / K2_BT);  // (125, 8)
    k2_score<<<grid, K2_THREADS>>>(emb, out);
}